// round 1
// baseline (speedup 1.0000x reference)
#include <cuda_runtime.h>
#include <math.h>

#define B_  8
#define C_  512
#define S_  2048
#define L_  8921
#define LT  16
#define NT  512
#define SSTAGE 32
#define SP  513   // stage pitch (pad: 513 % 32 == 1 -> conflict-free)

#define SWT_FLOATS   (LT * S_)        // 32768 (128 KB) weights
#define STAGE_FLOATS (SSTAGE * SP)    // 16416 (64.1 KB) stage / W_attn tile
#define RED_FLOATS   (LT * 16)        // 256
#define SMEM_FLOATS  (SWT_FLOATS + STAGE_FLOATS + RED_FLOATS + 2 * LT)
#define SMEM_BYTES   (SMEM_FLOATS * 4)

__global__ __launch_bounds__(NT, 1)
void hd_fused_kernel(const float* __restrict__ encoded,
                     const float* __restrict__ W_attn,
                     const float* __restrict__ W_cls,
                     const float* __restrict__ b_cls,
                     float* __restrict__ out)
{
    extern __shared__ float sm[];
    float* sWt    = sm;                       // [LT][S_] softmax weights
    float* sStage = sm + SWT_FLOATS;          // stage / W_attn tile (union)
    float* sRed   = sStage + STAGE_FLOATS;    // [LT][16] reduce scratch
    float* sFinA  = sRed + RED_FLOATS;        // [LT] max
    float* sFinB  = sFinA + LT;               // [LT] 1/sum

    const int tid  = threadIdx.x;
    const int lane = tid & 31;
    const int warp = tid >> 5;
    const int b    = blockIdx.y;
    const int l0   = blockIdx.x * LT;

    const float*  encb = encoded + (size_t)b * (C_ * (size_t)S_);
    const float4* enc4 = (const float4*)encb;   // element (c, s/4): enc4[c*(S_/4) + s/4]

    // ---- load W_attn tile (LT x C_) into stage region ----
    float* sW = sStage;
    #pragma unroll
    for (int i = 0; i < (LT * C_) / NT; i++) {
        int idx = tid + i * NT;
        int l = idx >> 9;            // / C_
        int c = idx & (C_ - 1);
        int gl = l0 + l;
        sW[idx] = (gl < L_) ? W_attn[(size_t)gl * C_ + c] : 0.0f;
    }
    __syncthreads();

    // ---- pass 1: scores for s = 4*tid..4*tid+3, all LT labels ----
    float acc[LT][4];
    #pragma unroll
    for (int l = 0; l < LT; l++) { acc[l][0] = acc[l][1] = acc[l][2] = acc[l][3] = 0.f; }

    float4 n0 = enc4[0 * (S_ / 4) + tid];
    float4 n1 = enc4[1 * (S_ / 4) + tid];
    float4 n2 = enc4[2 * (S_ / 4) + tid];
    float4 n3 = enc4[3 * (S_ / 4) + tid];

    #pragma unroll 1
    for (int c = 0; c < C_; c += 4) {
        float4 e0 = n0, e1 = n1, e2 = n2, e3 = n3;
        if (c + 4 < C_) {                                   // prefetch next chunk
            n0 = enc4[(c + 4) * (S_ / 4) + tid];
            n1 = enc4[(c + 5) * (S_ / 4) + tid];
            n2 = enc4[(c + 6) * (S_ / 4) + tid];
            n3 = enc4[(c + 7) * (S_ / 4) + tid];
        }
        #pragma unroll
        for (int l = 0; l < LT; l++) {
            const float4 w = *(const float4*)&sW[l * C_ + c];
            acc[l][0] = fmaf(w.x, e0.x, fmaf(w.y, e1.x, fmaf(w.z, e2.x, fmaf(w.w, e3.x, acc[l][0]))));
            acc[l][1] = fmaf(w.x, e0.y, fmaf(w.y, e1.y, fmaf(w.z, e2.y, fmaf(w.w, e3.y, acc[l][1]))));
            acc[l][2] = fmaf(w.x, e0.z, fmaf(w.y, e1.z, fmaf(w.z, e2.z, fmaf(w.w, e3.z, acc[l][2]))));
            acc[l][3] = fmaf(w.x, e0.w, fmaf(w.y, e1.w, fmaf(w.z, e2.w, fmaf(w.w, e3.w, acc[l][3]))));
        }
    }

    // ---- softmax over S per label (b_attn is constant over S: cancels) ----
    float Mv[LT];
    #pragma unroll
    for (int l = 0; l < LT; l++) {
        float m = fmaxf(fmaxf(acc[l][0], acc[l][1]), fmaxf(acc[l][2], acc[l][3]));
        #pragma unroll
        for (int off = 16; off > 0; off >>= 1)
            m = fmaxf(m, __shfl_xor_sync(0xffffffffu, m, off));
        if (lane == 0) sRed[l * 16 + warp] = m;
    }
    __syncthreads();
    if (tid < LT) {
        float m = -INFINITY;
        #pragma unroll
        for (int w = 0; w < 16; w++) m = fmaxf(m, sRed[tid * 16 + w]);
        sFinA[tid] = m;
    }
    __syncthreads();
    #pragma unroll
    for (int l = 0; l < LT; l++) Mv[l] = sFinA[l];

    #pragma unroll
    for (int l = 0; l < LT; l++) {
        float s = 0.f;
        #pragma unroll
        for (int j = 0; j < 4; j++) {
            float e = __expf(acc[l][j] - Mv[l]);
            acc[l][j] = e;
            s += e;
        }
        #pragma unroll
        for (int off = 16; off > 0; off >>= 1)
            s += __shfl_xor_sync(0xffffffffu, s, off);
        if (lane == 0) sRed[l * 16 + warp] = s;
    }
    __syncthreads();
    if (tid < LT) {
        float s = 0.f;
        #pragma unroll
        for (int w = 0; w < 16; w++) s += sRed[tid * 16 + w];
        sFinB[tid] = 1.0f / s;
    }
    __syncthreads();

    #pragma unroll
    for (int l = 0; l < LT; l++) {
        float inv = sFinB[l];
        float4 w4 = make_float4(acc[l][0] * inv, acc[l][1] * inv,
                                acc[l][2] * inv, acc[l][3] * inv);
        *(float4*)&sWt[l * S_ + 4 * tid] = w4;
    }
    // sWt visibility guaranteed by the barrier pair at the top of the pass-2 loop.

    // ---- pass 2: context[l][c=tid] = sum_s wt[l][s] * enc[c][s] ----
    float ctx[LT];
    #pragma unroll
    for (int l = 0; l < LT; l++) ctx[l] = 0.f;

    #pragma unroll 1
    for (int s0 = 0; s0 < S_; s0 += SSTAGE) {
        __syncthreads();   // stage reuse + (first iter) sWt written by all threads
        #pragma unroll
        for (int i = 0; i < (C_ * SSTAGE / 4) / NT; i++) {   // 8 iters
            int idx = tid + i * NT;          // 0..4095
            int cr  = idx >> 3;              // channel row
            int s4  = (idx & 7) << 2;        // s offset within tile
            float4 v = enc4[cr * (S_ / 4) + ((s0 + s4) >> 2)];
            sStage[(s4 + 0) * SP + cr] = v.x;
            sStage[(s4 + 1) * SP + cr] = v.y;
            sStage[(s4 + 2) * SP + cr] = v.z;
            sStage[(s4 + 3) * SP + cr] = v.w;
        }
        __syncthreads();
        #pragma unroll
        for (int sl = 0; sl < SSTAGE; sl += 4) {
            float e0 = sStage[(sl + 0) * SP + tid];
            float e1 = sStage[(sl + 1) * SP + tid];
            float e2 = sStage[(sl + 2) * SP + tid];
            float e3 = sStage[(sl + 3) * SP + tid];
            #pragma unroll
            for (int l = 0; l < LT; l++) {
                const float4 w = *(const float4*)&sWt[l * S_ + s0 + sl];
                ctx[l] = fmaf(w.x, e0, fmaf(w.y, e1, fmaf(w.z, e2, fmaf(w.w, e3, ctx[l]))));
            }
        }
    }

    // ---- final: logits[l] = sum_c ctx[l][c] * W_cls[l][c] + b_cls[l] ----
    #pragma unroll
    for (int l = 0; l < LT; l++) {
        int gl = l0 + l;
        float wc = (gl < L_) ? W_cls[(size_t)gl * C_ + tid] : 0.f;
        float v = ctx[l] * wc;
        #pragma unroll
        for (int off = 16; off > 0; off >>= 1)
            v += __shfl_xor_sync(0xffffffffu, v, off);
        if (lane == 0) sRed[l * 16 + warp] = v;
    }
    __syncthreads();
    if (tid < LT) {
        int gl = l0 + tid;
        if (gl < L_) {
            float s = 0.f;
            #pragma unroll
            for (int w = 0; w < 16; w++) s += sRed[tid * 16 + w];
            out[(size_t)b * L_ + gl] = s + b_cls[gl];
        }
    }
}

extern "C" void kernel_launch(void* const* d_in, const int* in_sizes, int n_in,
                              void* d_out, int out_size)
{
    const float* encoded = (const float*)d_in[0];
    const float* W_attn  = (const float*)d_in[1];
    // d_in[2] = b_attn: constant along the softmax axis -> provably no effect on output
    const float* W_cls   = (const float*)d_in[3];
    const float* b_cls   = (const float*)d_in[4];
    float* out = (float*)d_out;

    cudaFuncSetAttribute(hd_fused_kernel,
                         cudaFuncAttributeMaxDynamicSharedMemorySize, SMEM_BYTES);

    dim3 grid((L_ + LT - 1) / LT, B_);
    hd_fused_kernel<<<grid, NT, SMEM_BYTES>>>(encoded, W_attn, W_cls, b_cls, out);
}

// round 2
// speedup vs baseline: 1.2534x; 1.2534x over previous
#include <cuda_runtime.h>
#include <math.h>

#define B_  8
#define C_  512
#define S_  2048
#define L_  8921
#define LT  16
#define LPAIR 8
#define NT  512
#define SSTAGE 32
#define SP  513          // stage pitch: 513 % 32 == 1 -> conflict-free scalar access
#define WTP 16           // sWt2 row pitch (floats) = LT labels interleaved

#define SWT_FLOATS   (S_ * WTP)        // 32768 (128 KB) label-interleaved softmax weights
#define UNION_FLOATS (SSTAGE * SP)     // 16416 (64.1 KB): W_attn tile (pass1) / enc stage (pass2)
#define RED_FLOATS   (LT * 16)
#define SMEM_FLOATS  (SWT_FLOATS + UNION_FLOATS + RED_FLOATS + 2 * LT)
#define SMEM_BYTES   (SMEM_FLOATS * 4)

typedef unsigned long long u64;

__device__ __forceinline__ u64 pk2(float x, float y) {
    u64 r; asm("mov.b64 %0, {%1,%2};" : "=l"(r) : "f"(x), "f"(y)); return r;
}
__device__ __forceinline__ u64 dup2(float x) { return pk2(x, x); }
__device__ __forceinline__ void up2(u64 v, float& x, float& y) {
    asm("mov.b64 {%0,%1}, %2;" : "=f"(x), "=f"(y) : "l"(v));
}
// d += a * b  on packed f32x2  (SASS: FFMA2 — 2 fp32 FMA per issue slot)
__device__ __forceinline__ void ffma2(u64& d, u64 a, u64 b) {
    asm("fma.rn.f32x2 %0, %1, %2, %0;" : "+l"(d) : "l"(a), "l"(b));
}

__global__ __launch_bounds__(NT, 1)
void hd_fused_kernel(const float* __restrict__ encoded,
                     const float* __restrict__ W_attn,
                     const float* __restrict__ W_cls,
                     const float* __restrict__ b_cls,
                     float* __restrict__ out)
{
    extern __shared__ float sm[];
    float* sWt2   = sm;                       // [S_][WTP] weights, labels interleaved
    float* sUni   = sm + SWT_FLOATS;          // union: sW2 (pass1) / stage (pass2)
    float* sRed   = sUni + UNION_FLOATS;      // [LT][16]
    float* sFinA  = sRed + RED_FLOATS;        // [LT] max
    float* sFinB  = sFinA + LT;               // [LT] 1/sum

    const int tid  = threadIdx.x;
    const int lane = tid & 31;
    const int warp = tid >> 5;
    const int b    = blockIdx.y;
    const int l0   = blockIdx.x * LT;

    const float*  encb = encoded + (size_t)b * (C_ * (size_t)S_);
    const float4* enc4 = (const float4*)encb;

    // ---- load W_attn tile, label-interleaved: sW2[c*16 + j] = W_attn[l0+j][c] ----
    float* sW2 = sUni;
    #pragma unroll
    for (int i = 0; i < (LT * C_) / NT; i++) {          // 16 iters
        int idx = tid + i * NT;
        int c = idx >> 4;
        int j = idx & 15;
        int gl = l0 + j;
        sW2[c * 16 + j] = (gl < L_) ? W_attn[(size_t)gl * C_ + c] : 0.0f;
    }
    __syncthreads();

    // ---- pass 1: scores, packed over label pairs. acc2[lp][j] = (l=2lp, l=2lp+1) at s=4tid+j
    u64 acc2[LPAIR][4];
    #pragma unroll
    for (int lp = 0; lp < LPAIR; lp++)
        #pragma unroll
        for (int j = 0; j < 4; j++) acc2[lp][j] = 0ULL;

    float4 n0 = enc4[0 * (S_ / 4) + tid];
    float4 n1 = enc4[1 * (S_ / 4) + tid];
    float4 n2 = enc4[2 * (S_ / 4) + tid];
    float4 n3 = enc4[3 * (S_ / 4) + tid];

    #pragma unroll 1
    for (int c = 0; c < C_; c += 4) {
        float4 e[4] = { n0, n1, n2, n3 };
        if (c + 4 < C_) {
            n0 = enc4[(c + 4) * (S_ / 4) + tid];
            n1 = enc4[(c + 5) * (S_ / 4) + tid];
            n2 = enc4[(c + 6) * (S_ / 4) + tid];
            n3 = enc4[(c + 7) * (S_ / 4) + tid];
        }
        #pragma unroll
        for (int cc = 0; cc < 4; cc++) {
            const ulonglong2* wr = (const ulonglong2*)&sW2[(c + cc) * 16];
            ulonglong2 wA = wr[0], wB = wr[1], wC = wr[2], wD = wr[3];   // lp 0..7
            u64 d0 = dup2(e[cc].x), d1 = dup2(e[cc].y);
            u64 d2 = dup2(e[cc].z), d3 = dup2(e[cc].w);
            ffma2(acc2[0][0], d0, wA.x); ffma2(acc2[1][0], d0, wA.y);
            ffma2(acc2[2][0], d0, wB.x); ffma2(acc2[3][0], d0, wB.y);
            ffma2(acc2[4][0], d0, wC.x); ffma2(acc2[5][0], d0, wC.y);
            ffma2(acc2[6][0], d0, wD.x); ffma2(acc2[7][0], d0, wD.y);
            ffma2(acc2[0][1], d1, wA.x); ffma2(acc2[1][1], d1, wA.y);
            ffma2(acc2[2][1], d1, wB.x); ffma2(acc2[3][1], d1, wB.y);
            ffma2(acc2[4][1], d1, wC.x); ffma2(acc2[5][1], d1, wC.y);
            ffma2(acc2[6][1], d1, wD.x); ffma2(acc2[7][1], d1, wD.y);
            ffma2(acc2[0][2], d2, wA.x); ffma2(acc2[1][2], d2, wA.y);
            ffma2(acc2[2][2], d2, wB.x); ffma2(acc2[3][2], d2, wB.y);
            ffma2(acc2[4][2], d2, wC.x); ffma2(acc2[5][2], d2, wC.y);
            ffma2(acc2[6][2], d2, wD.x); ffma2(acc2[7][2], d2, wD.y);
            ffma2(acc2[0][3], d3, wA.x); ffma2(acc2[1][3], d3, wA.y);
            ffma2(acc2[2][3], d3, wB.x); ffma2(acc2[3][3], d3, wB.y);
            ffma2(acc2[4][3], d3, wC.x); ffma2(acc2[5][3], d3, wC.y);
            ffma2(acc2[6][3], d3, wD.x); ffma2(acc2[7][3], d3, wD.y);
        }
    }

    // ---- unpack to per-label scores ----
    float sc[LT][4];
    #pragma unroll
    for (int lp = 0; lp < LPAIR; lp++)
        #pragma unroll
        for (int j = 0; j < 4; j++)
            up2(acc2[lp][j], sc[2 * lp][j], sc[2 * lp + 1][j]);

    // ---- softmax over S per label (b_attn constant over S: cancels) ----
    float Mv[LT];
    #pragma unroll
    for (int l = 0; l < LT; l++) {
        float m = fmaxf(fmaxf(sc[l][0], sc[l][1]), fmaxf(sc[l][2], sc[l][3]));
        #pragma unroll
        for (int off = 16; off > 0; off >>= 1)
            m = fmaxf(m, __shfl_xor_sync(0xffffffffu, m, off));
        if (lane == 0) sRed[l * 16 + warp] = m;
    }
    __syncthreads();
    if (tid < LT) {
        float m = -INFINITY;
        #pragma unroll
        for (int w = 0; w < 16; w++) m = fmaxf(m, sRed[tid * 16 + w]);
        sFinA[tid] = m;
    }
    __syncthreads();
    #pragma unroll
    for (int l = 0; l < LT; l++) Mv[l] = sFinA[l];

    #pragma unroll
    for (int l = 0; l < LT; l++) {
        float s = 0.f;
        #pragma unroll
        for (int j = 0; j < 4; j++) {
            float e = __expf(sc[l][j] - Mv[l]);
            sc[l][j] = e;
            s += e;
        }
        #pragma unroll
        for (int off = 16; off > 0; off >>= 1)
            s += __shfl_xor_sync(0xffffffffu, s, off);
        if (lane == 0) sRed[l * 16 + warp] = s;
    }
    __syncthreads();
    if (tid < LT) {
        float s = 0.f;
        #pragma unroll
        for (int w = 0; w < 16; w++) s += sRed[tid * 16 + w];
        sFinB[tid] = 1.0f / s;
    }
    __syncthreads();

    // ---- store normalized weights, label-interleaved rows: sWt2[(4tid+j)*16 + l] ----
    #pragma unroll
    for (int j = 0; j < 4; j++) {
        float4* row = (float4*)&sWt2[(4 * tid + j) * WTP];
        #pragma unroll
        for (int m = 0; m < 4; m++) {
            row[m] = make_float4(sc[4 * m + 0][j] * sFinB[4 * m + 0],
                                 sc[4 * m + 1][j] * sFinB[4 * m + 1],
                                 sc[4 * m + 2][j] * sFinB[4 * m + 2],
                                 sc[4 * m + 3][j] * sFinB[4 * m + 3]);
        }
    }
    // visibility: barrier at top of pass-2 tile loop

    // ---- pass 2: ctx2[lp][k] partial over this thread's s-range, channels cq+128k ----
    const int p  = tid >> 7;        // s-subrange within each tile (rows p*8..p*8+7)
    const int cq = tid & 127;
    float* sStage = sUni;

    u64 ctx2[LPAIR][4];
    #pragma unroll
    for (int lp = 0; lp < LPAIR; lp++)
        #pragma unroll
        for (int k = 0; k < 4; k++) ctx2[lp][k] = 0ULL;

    #pragma unroll 1
    for (int s0 = 0; s0 < S_; s0 += SSTAGE) {
        __syncthreads();
        #pragma unroll
        for (int i = 0; i < (C_ * SSTAGE / 4) / NT; i++) {   // 8 iters
            int idx = tid + i * NT;
            int cr  = idx >> 3;
            int s4  = (idx & 7) << 2;
            float4 v = enc4[cr * (S_ / 4) + ((s0 + s4) >> 2)];
            sStage[(s4 + 0) * SP + cr] = v.x;
            sStage[(s4 + 1) * SP + cr] = v.y;
            sStage[(s4 + 2) * SP + cr] = v.z;
            sStage[(s4 + 3) * SP + cr] = v.w;
        }
        __syncthreads();

        #pragma unroll
        for (int half = 0; half < 2; half++) {
            int slb = p * 8 + half * 4;
            #pragma unroll
            for (int j = 0; j < 4; j++) {
                int sl = slb + j;
                const ulonglong2* wr = (const ulonglong2*)&sWt2[(s0 + sl) * WTP];
                ulonglong2 wA = wr[0], wB = wr[1], wC = wr[2], wD = wr[3];
                #pragma unroll
                for (int k = 0; k < 4; k++) {
                    u64 e = dup2(sStage[sl * SP + cq + 128 * k]);
                    ffma2(ctx2[0][k], e, wA.x); ffma2(ctx2[1][k], e, wA.y);
                    ffma2(ctx2[2][k], e, wB.x); ffma2(ctx2[3][k], e, wB.y);
                    ffma2(ctx2[4][k], e, wC.x); ffma2(ctx2[5][k], e, wC.y);
                    ffma2(ctx2[6][k], e, wD.x); ffma2(ctx2[7][k], e, wD.y);
                }
            }
        }
    }

    // ---- final: logits[l] = sum_{threads} sum_k ctx[l][k] * W_cls[l][cq+128k] + b_cls ----
    #pragma unroll
    for (int l = 0; l < LT; l++) {
        int gl = l0 + l;
        float v = 0.f;
        if (gl < L_) {
            const float* wrow = W_cls + (size_t)gl * C_ + cq;
            #pragma unroll
            for (int k = 0; k < 4; k++) {
                float lo, hi;
                up2(ctx2[l >> 1][k], lo, hi);
                float cv = (l & 1) ? hi : lo;
                v += cv * wrow[128 * k];
            }
        }
        #pragma unroll
        for (int off = 16; off > 0; off >>= 1)
            v += __shfl_xor_sync(0xffffffffu, v, off);
        if (lane == 0) sRed[l * 16 + warp] = v;
    }
    __syncthreads();
    if (tid < LT) {
        int gl = l0 + tid;
        if (gl < L_) {
            float s = 0.f;
            #pragma unroll
            for (int w = 0; w < 16; w++) s += sRed[tid * 16 + w];
            out[(size_t)b * L_ + gl] = s + b_cls[gl];
        }
    }
}

extern "C" void kernel_launch(void* const* d_in, const int* in_sizes, int n_in,
                              void* d_out, int out_size)
{
    const float* encoded = (const float*)d_in[0];
    const float* W_attn  = (const float*)d_in[1];
    // d_in[2] = b_attn: constant along the softmax axis -> no effect on output
    const float* W_cls   = (const float*)d_in[3];
    const float* b_cls   = (const float*)d_in[4];
    float* out = (float*)d_out;

    cudaFuncSetAttribute(hd_fused_kernel,
                         cudaFuncAttributeMaxDynamicSharedMemorySize, SMEM_BYTES);

    dim3 grid((L_ + LT - 1) / LT, B_);
    hd_fused_kernel<<<grid, NT, SMEM_BYTES>>>(encoded, W_attn, W_cls, b_cls, out);
}

// round 8
// speedup vs baseline: 9.4395x; 7.5310x over previous
#include <cuda_runtime.h>
#include <cuda_fp16.h>
#include <cstdint>

#define B_   8
#define C_   512
#define S_   2048
#define L_   8921
#define LPAD 8960
#define NLT  70

// ---------------- device scratch ----------------
__device__ __align__(16) __half g_encB[B_][C_][S_];   // [b][c][s]
__device__ __align__(16) __half g_encT[B_][S_][C_];   // [b][s][c]
__device__ __align__(16) __half g_wB[LPAD][C_];
__device__ __align__(16) __half g_P[B_][LPAD][S_];    // exp(scores)
__device__ float g_Zinv[B_][LPAD];

// ---------------- helpers ----------------
__device__ __forceinline__ uint32_t smem_u32(const void* p) {
    uint32_t a;
    asm("{ .reg .u64 t; cvta.to.shared.u64 t, %1; cvt.u32.u64 %0, t; }" : "=r"(a) : "l"(p));
    return a;
}
#define CPA(dst, src) \
    asm volatile("cp.async.cg.shared.global [%0], [%1], 16;" :: "r"(dst), "l"(src))
#define CPC() asm volatile("cp.async.commit_group;" ::: "memory")
#define CPW(n) asm volatile("cp.async.wait_group %0;" :: "n"(n) : "memory")

__device__ __forceinline__ void ldsm4(uint32_t* r, uint32_t addr) {
    asm volatile("ldmatrix.sync.aligned.m8n8.x4.shared.b16 {%0,%1,%2,%3}, [%4];"
        : "=r"(r[0]), "=r"(r[1]), "=r"(r[2]), "=r"(r[3]) : "r"(addr));
}
__device__ __forceinline__ void mma16816(float* d, const uint32_t* a, const uint32_t* b) {
    asm volatile("mma.sync.aligned.m16n8k16.row.col.f32.f16.f16.f32 "
        "{%0,%1,%2,%3}, {%4,%5,%6,%7}, {%8,%9}, {%0,%1,%2,%3};"
        : "+f"(d[0]), "+f"(d[1]), "+f"(d[2]), "+f"(d[3])
        : "r"(a[0]), "r"(a[1]), "r"(a[2]), "r"(a[3]), "r"(b[0]), "r"(b[1]));
}

// ---------------- prep kernels ----------------
__global__ void prep_enc(const float* __restrict__ enc) {
    __shared__ float t[32][33];
    int b = blockIdx.z, c0 = blockIdx.x * 32, s0 = blockIdx.y * 32;
    int tx = threadIdx.x & 31, ty = threadIdx.x >> 5;   // 256 threads: 32x8
    #pragma unroll
    for (int r = 0; r < 4; r++) {
        int c = c0 + ty + 8 * r;
        float v = enc[((size_t)b * C_ + c) * S_ + s0 + tx];
        t[ty + 8 * r][tx] = v;
        g_encB[b][c][s0 + tx] = __float2half(v);
    }
    __syncthreads();
    #pragma unroll
    for (int r = 0; r < 4; r++) {
        int s = s0 + ty + 8 * r;
        g_encT[b][s][c0 + tx] = __float2half(t[tx][ty + 8 * r]);
    }
}
__global__ void prep_w(const float* __restrict__ W) {
    int i = blockIdx.x * blockDim.x + threadIdx.x;
    int l = i >> 9, c = i & (C_ - 1);
    g_wB[l][c] = __float2half(l < L_ ? W[(size_t)l * C_ + c] : 0.0f);
}
__global__ void out_init(const float* __restrict__ b_cls, float* __restrict__ out) {
    int i = blockIdx.x * blockDim.x + threadIdx.x;
    if (i < B_ * L_) out[i] = b_cls[i % L_];
}

// ---------------- K1: scores + exp + Z ----------------
// CTA: 128 labels x 256 s per chunk, K=C=512. A (W tile) resident, B double-buffered.
#define K1_SMEM (512 + 131072 + 2 * 32768)

__global__ __launch_bounds__(256, 1) void k1_scores() {
    extern __shared__ char sm[];
    float* zs = (float*)sm;
    char* sA = sm + 512;
    char* sB = sm + 512 + 131072;
    const uint32_t sAu = smem_u32(sA), sBu = smem_u32(sB);
    const int tid = threadIdx.x, lane = tid & 31, wid = tid >> 5;
    const int wm = (wid >> 2) * 64, wn = (wid & 3) * 64;
    const int b = blockIdx.y, l0 = blockIdx.x * 128;

    if (tid < 128) zs[tid] = 0.f;

    // stage A: 128x512 -> 8 subtiles [128][64], 16B-XOR swizzled
    #pragma unroll
    for (int j = 0; j < 32; j++) {
        int lin = j * 256 + tid;
        int row = lin >> 6, seg = lin & 63;
        uint4 v = *(const uint4*)&g_wB[l0 + row][seg * 8];
        *(uint4*)(sA + (seg >> 3) * 16384 + row * 128 +
                  (((seg & 7) * 16) ^ ((row & 7) << 4))) = v;
    }
    __syncthreads();

    const int swz   = (lane & 7) << 4;
    const int arow  = lane & 15;                         // A: + wm + mt*16
    const int acolb = (lane >> 4) << 4;                  // A: + k0*2
    const int brow  = (lane & 7) + ((lane >> 4) << 3);   // B: + wn + ng*16
    const int bcolb = ((lane >> 3) & 1) << 4;            // B: + k0*2

    float acc[4][8][4];
    float zr[4][2];
    #pragma unroll
    for (int mt = 0; mt < 4; mt++) { zr[mt][0] = 0.f; zr[mt][1] = 0.f; }

    // prologue: stage B chunk for it=0 (s-chunk 0, k-chunk 0)
    #pragma unroll
    for (int j = 0; j < 8; j++) {
        int lin = j * 256 + tid;
        int row = lin >> 3, c16 = lin & 7;
        CPA(sBu + row * 128 + ((c16 * 16) ^ ((row & 7) << 4)),
            (const char*)&g_encT[b][row][c16 * 8]);
    }
    CPC();

    #pragma unroll 1
    for (int it = 0; it < 64; it++) {
        const int n = it >> 3, kk = it & 7;
        const uint32_t bufo = (uint32_t)(it & 1) * 32768u;

        if (kk == 0) {
            #pragma unroll
            for (int mt = 0; mt < 4; mt++)
                #pragma unroll
                for (int nt = 0; nt < 8; nt++)
                    acc[mt][nt][0] = acc[mt][nt][1] = acc[mt][nt][2] = acc[mt][nt][3] = 0.f;
        }

        if (it < 63) {
            const int n2 = (it + 1) >> 3, k2 = (it + 1) & 7;
            const uint32_t bo2 = (uint32_t)((it + 1) & 1) * 32768u;
            #pragma unroll
            for (int j = 0; j < 8; j++) {
                int lin = j * 256 + tid;
                int row = lin >> 3, c16 = lin & 7;
                CPA(sBu + bo2 + row * 128 + ((c16 * 16) ^ ((row & 7) << 4)),
                    (const char*)&g_encT[b][n2 * 256 + row][k2 * 64 + c16 * 8]);
            }
            CPC();
            CPW(1);
        } else {
            CPW(0);
        }
        __syncthreads();

        const uint32_t aB = sAu + kk * 16384;
        #pragma unroll
        for (int ks = 0; ks < 4; ks++) {
            const int k0b = ks * 32;
            uint32_t a[4][4], bfr[4][4];
            #pragma unroll
            for (int mt = 0; mt < 4; mt++)
                ldsm4(a[mt], aB + (wm + mt * 16 + arow) * 128 + ((k0b + acolb) ^ swz));
            #pragma unroll
            for (int ng = 0; ng < 4; ng++)
                ldsm4(bfr[ng], sBu + bufo + (wn + ng * 16 + brow) * 128 + ((k0b + bcolb) ^ swz));
            #pragma unroll
            for (int mt = 0; mt < 4; mt++)
                #pragma unroll
                for (int ng = 0; ng < 4; ng++) {
                    mma16816(acc[mt][2 * ng],     a[mt], &bfr[ng][0]);
                    mma16816(acc[mt][2 * ng + 1], a[mt], &bfr[ng][2]);
                }
        }
        __syncthreads();   // protect buffer before re-stage next iteration

        if (kk == 7) {     // epilogue: exp, store P, accumulate Z
            const int sg = n * 256 + wn;
            #pragma unroll
            for (int mt = 0; mt < 4; mt++) {
                const int r0 = l0 + wm + mt * 16 + (lane >> 2);
                #pragma unroll
                for (int nt = 0; nt < 8; nt++) {
                    const int sc = sg + nt * 8 + ((lane & 3) << 1);
                    float e0 = __expf(acc[mt][nt][0]);
                    float e1 = __expf(acc[mt][nt][1]);
                    float e2 = __expf(acc[mt][nt][2]);
                    float e3 = __expf(acc[mt][nt][3]);
                    zr[mt][0] += e0 + e1;
                    zr[mt][1] += e2 + e3;
                    *(__half2*)&g_P[b][r0][sc]     = __floats2half2_rn(e0, e1);
                    *(__half2*)&g_P[b][r0 + 8][sc] = __floats2half2_rn(e2, e3);
                }
            }
        }
    }

    #pragma unroll
    for (int mt = 0; mt < 4; mt++) {
        atomicAdd(&zs[wm + mt * 16 + (lane >> 2)],     zr[mt][0]);
        atomicAdd(&zs[wm + mt * 16 + (lane >> 2) + 8], zr[mt][1]);
    }
    __syncthreads();
    if (tid < 128) g_Zinv[b][l0 + tid] = 1.0f / zs[tid];
}

// ---------------- K2: context + classifier ----------------
// CTA: 128 labels x 256 channels, K=S=2048 in chunks of 64. Both operands double-buffered.
#define K2_SMEM (512 + 2 * 16384 + 2 * 32768)

__global__ __launch_bounds__(256, 1) void k2_context(const float* __restrict__ W_cls,
                                                     float* __restrict__ out) {
    extern __shared__ char sm[];
    float* red = (float*)sm;
    char* sA = sm + 512;
    char* sB = sm + 512 + 32768;
    const uint32_t sAu = smem_u32(sA), sBu = smem_u32(sB);
    const int tid = threadIdx.x, lane = tid & 31, wid = tid >> 5;
    const int wm = (wid >> 2) * 64, wn = (wid & 3) * 64;
    const int b = blockIdx.z, l0 = blockIdx.x * 128, c0 = blockIdx.y * 256;

    if (tid < 128) red[tid] = 0.f;

    const int swz   = (lane & 7) << 4;
    const int arow  = lane & 15;
    const int acolb = (lane >> 4) << 4;
    const int brow  = (lane & 7) + ((lane >> 4) << 3);
    const int bcolb = ((lane >> 3) & 1) << 4;

    float acc[4][8][4];
    #pragma unroll
    for (int mt = 0; mt < 4; mt++)
        #pragma unroll
        for (int nt = 0; nt < 8; nt++)
            acc[mt][nt][0] = acc[mt][nt][1] = acc[mt][nt][2] = acc[mt][nt][3] = 0.f;

    // prologue stage it=0
    #pragma unroll
    for (int j = 0; j < 4; j++) {
        int lin = j * 256 + tid;
        int row = lin >> 3, c16 = lin & 7;
        CPA(sAu + row * 128 + ((c16 * 16) ^ ((row & 7) << 4)),
            (const char*)&g_P[b][l0 + row][c16 * 8]);
    }
    #pragma unroll
    for (int j = 0; j < 8; j++) {
        int lin = j * 256 + tid;
        int row = lin >> 3, c16 = lin & 7;
        CPA(sBu + row * 128 + ((c16 * 16) ^ ((row & 7) << 4)),
            (const char*)&g_encB[b][c0 + row][c16 * 8]);
    }
    CPC();

    #pragma unroll 1
    for (int it = 0; it < 32; it++) {
        const uint32_t aBuf = (uint32_t)(it & 1) * 16384u;
        const uint32_t bBuf = (uint32_t)(it & 1) * 32768u;

        if (it < 31) {
            const int s2 = (it + 1) * 64;
            const uint32_t a2 = (uint32_t)((it + 1) & 1) * 16384u;
            const uint32_t b2 = (uint32_t)((it + 1) & 1) * 32768u;
            #pragma unroll
            for (int j = 0; j < 4; j++) {
                int lin = j * 256 + tid;
                int row = lin >> 3, c16 = lin & 7;
                CPA(sAu + a2 + row * 128 + ((c16 * 16) ^ ((row & 7) << 4)),
                    (const char*)&g_P[b][l0 + row][s2 + c16 * 8]);
            }
            #pragma unroll
            for (int j = 0; j < 8; j++) {
                int lin = j * 256 + tid;
                int row = lin >> 3, c16 = lin & 7;
                CPA(sBu + b2 + row * 128 + ((c16 * 16) ^ ((row & 7) << 4)),
                    (const char*)&g_encB[b][c0 + row][s2 + c16 * 8]);
            }
            CPC();
            CPW(1);
        } else {
            CPW(0);
        }
        __syncthreads();

        #pragma unroll
        for (int ks = 0; ks < 4; ks++) {
            const int k0b = ks * 32;
            uint32_t a[4][4], bfr[4][4];
            #pragma unroll
            for (int mt = 0; mt < 4; mt++)
                ldsm4(a[mt], sAu + aBuf + (wm + mt * 16 + arow) * 128 + ((k0b + acolb) ^ swz));
            #pragma unroll
            for (int ng = 0; ng < 4; ng++)
                ldsm4(bfr[ng], sBu + bBuf + (wn + ng * 16 + brow) * 128 + ((k0b + bcolb) ^ swz));
            #pragma unroll
            for (int mt = 0; mt < 4; mt++)
                #pragma unroll
                for (int ng = 0; ng < 4; ng++) {
                    mma16816(acc[mt][2 * ng],     a[mt], &bfr[ng][0]);
                    mma16816(acc[mt][2 * ng + 1], a[mt], &bfr[ng][2]);
                }
        }
        __syncthreads();
    }

    // epilogue: diagonal classifier dot + CTA reduce + global atomic
    #pragma unroll
    for (int mt = 0; mt < 4; mt++) {
        const int lloc = wm + mt * 16 + (lane >> 2);
        const int gl0 = l0 + lloc, gl1 = gl0 + 8;
        float v0 = 0.f, v1 = 0.f;
        #pragma unroll
        for (int nt = 0; nt < 8; nt++) {
            const int c = c0 + wn + nt * 8 + ((lane & 3) << 1);
            if (gl0 < L_) {
                const float* w = &W_cls[(size_t)gl0 * C_ + c];
                v0 += acc[mt][nt][0] * w[0] + acc[mt][nt][1] * w[1];
            }
            if (gl1 < L_) {
                const float* w = &W_cls[(size_t)gl1 * C_ + c];
                v1 += acc[mt][nt][2] * w[0] + acc[mt][nt][3] * w[1];
            }
        }
        atomicAdd(&red[lloc],     v0);
        atomicAdd(&red[lloc + 8], v1);
    }
    __syncthreads();
    if (tid < 128) {
        const int gl = l0 + tid;
        if (gl < L_)
            atomicAdd(&out[(size_t)b * L_ + gl], red[tid] * g_Zinv[b][gl]);
    }
}

// ---------------- launcher ----------------
extern "C" void kernel_launch(void* const* d_in, const int* in_sizes, int n_in,
                              void* d_out, int out_size) {
    const float* encoded = (const float*)d_in[0];
    const float* W_attn  = (const float*)d_in[1];
    // d_in[2] = b_attn: constant along the softmax axis -> no effect on output
    const float* W_cls   = (const float*)d_in[3];
    const float* b_cls   = (const float*)d_in[4];
    float* out = (float*)d_out;

    cudaFuncSetAttribute(k1_scores,  cudaFuncAttributeMaxDynamicSharedMemorySize, K1_SMEM);
    cudaFuncSetAttribute(k2_context, cudaFuncAttributeMaxDynamicSharedMemorySize, K2_SMEM);

    prep_enc<<<dim3(C_ / 32, S_ / 32, B_), 256>>>(encoded);
    prep_w<<<(LPAD * C_) / 256, 256>>>(W_attn);
    out_init<<<(B_ * L_ + 255) / 256, 256>>>(b_cls, out);
    k1_scores<<<dim3(NLT, B_), 256, K1_SMEM>>>();
    k2_context<<<dim3(NLT, 2, B_), 256, K2_SMEM>>>(W_cls, out);
}

// round 9
// speedup vs baseline: 9.7459x; 1.0325x over previous
#include <cuda_runtime.h>
#include <cuda_fp16.h>
#include <cstdint>

#define B_   8
#define C_   512
#define S_   2048
#define L_   8921
#define LPAD 8960
#define NLT  70

// ---------------- device scratch ----------------
__device__ __align__(16) __half g_encB[B_][C_][S_];   // [b][c][s]
__device__ __align__(16) __half g_encT[B_][S_][C_];   // [b][s][c]
__device__ __align__(16) __half g_wB[LPAD][C_];
__device__ __align__(16) __half g_P[B_][LPAD][S_];    // exp(scores)
__device__ float g_Zinv[B_][LPAD];

// ---------------- helpers ----------------
__device__ __forceinline__ uint32_t smem_u32(const void* p) {
    uint32_t a;
    asm("{ .reg .u64 t; cvta.to.shared.u64 t, %1; cvt.u32.u64 %0, t; }" : "=r"(a) : "l"(p));
    return a;
}
#define CPA(dst, src) \
    asm volatile("cp.async.cg.shared.global [%0], [%1], 16;" :: "r"(dst), "l"(src))
#define CPC() asm volatile("cp.async.commit_group;" ::: "memory")
#define CPW(n) asm volatile("cp.async.wait_group %0;" :: "n"(n) : "memory")

__device__ __forceinline__ void ldsm4(uint32_t* r, uint32_t addr) {
    asm volatile("ldmatrix.sync.aligned.m8n8.x4.shared.b16 {%0,%1,%2,%3}, [%4];"
        : "=r"(r[0]), "=r"(r[1]), "=r"(r[2]), "=r"(r[3]) : "r"(addr));
}
__device__ __forceinline__ void mma16816(float* d, const uint32_t* a, const uint32_t* b) {
    asm volatile("mma.sync.aligned.m16n8k16.row.col.f32.f16.f16.f32 "
        "{%0,%1,%2,%3}, {%4,%5,%6,%7}, {%8,%9}, {%0,%1,%2,%3};"
        : "+f"(d[0]), "+f"(d[1]), "+f"(d[2]), "+f"(d[3])
        : "r"(a[0]), "r"(a[1]), "r"(a[2]), "r"(a[3]), "r"(b[0]), "r"(b[1]));
}

// ---------------- prep kernels ----------------
__global__ void prep_enc(const float* __restrict__ enc) {
    __shared__ float t[32][33];
    int b = blockIdx.z, c0 = blockIdx.x * 32, s0 = blockIdx.y * 32;
    int tx = threadIdx.x & 31, ty = threadIdx.x >> 5;   // 256 threads: 32x8
    #pragma unroll
    for (int r = 0; r < 4; r++) {
        int c = c0 + ty + 8 * r;
        float v = enc[((size_t)b * C_ + c) * S_ + s0 + tx];
        t[ty + 8 * r][tx] = v;
        g_encB[b][c][s0 + tx] = __float2half(v);
    }
    __syncthreads();
    #pragma unroll
    for (int r = 0; r < 4; r++) {
        int s = s0 + ty + 8 * r;
        g_encT[b][s][c0 + tx] = __float2half(t[tx][ty + 8 * r]);
    }
}
__global__ void prep_w(const float* __restrict__ W) {
    int i = blockIdx.x * blockDim.x + threadIdx.x;
    int l = i >> 9, c = i & (C_ - 1);
    g_wB[l][c] = __float2half(l < L_ ? W[(size_t)l * C_ + c] : 0.0f);
}
__global__ void out_init(const float* __restrict__ b_cls, float* __restrict__ out) {
    int i = blockIdx.x * blockDim.x + threadIdx.x;
    if (i < B_ * L_) out[i] = b_cls[i % L_];
}

// ---------------- K1: scores + exp + Z ----------------
// CTA: 128 labels x 256 s per chunk, K=C=512. 512 threads, 16 warps of 32x64.
// A (W tile) resident, B double-buffered.
#define K1_SMEM (512 + 131072 + 2 * 32768)

__global__ __launch_bounds__(512, 1) void k1_scores() {
    extern __shared__ char sm[];
    float* zs = (float*)sm;
    char* sA = sm + 512;
    char* sB = sm + 512 + 131072;
    const uint32_t sAu = smem_u32(sA), sBu = smem_u32(sB);
    const int tid = threadIdx.x, lane = tid & 31, wid = tid >> 5;
    const int wm = (wid >> 2) * 32, wn = (wid & 3) * 64;
    const int b = blockIdx.y, l0 = blockIdx.x * 128;

    if (tid < 128) zs[tid] = 0.f;

    // stage A: 128x512 -> 8 subtiles [128][64], 16B-XOR swizzled
    #pragma unroll
    for (int j = 0; j < 16; j++) {
        int lin = j * 512 + tid;
        int row = lin >> 6, seg = lin & 63;
        uint4 v = *(const uint4*)&g_wB[l0 + row][seg * 8];
        *(uint4*)(sA + (seg >> 3) * 16384 + row * 128 +
                  (((seg & 7) * 16) ^ ((row & 7) << 4))) = v;
    }
    __syncthreads();

    const int swz   = (lane & 7) << 4;
    const int arow  = lane & 15;                         // A: + wm + mt*16
    const int acolb = (lane >> 4) << 4;                  // A: + k0*2
    const int brow  = (lane & 7) + ((lane >> 4) << 3);   // B: + wn + ng*16
    const int bcolb = ((lane >> 3) & 1) << 4;            // B: + k0*2

    float acc[2][8][4];
    float zr[2][2];
    #pragma unroll
    for (int mt = 0; mt < 2; mt++) { zr[mt][0] = 0.f; zr[mt][1] = 0.f; }

    // prologue: stage B chunk for it=0 (s-chunk 0, k-chunk 0)
    #pragma unroll
    for (int j = 0; j < 4; j++) {
        int lin = j * 512 + tid;
        int row = lin >> 3, c16 = lin & 7;
        CPA(sBu + row * 128 + ((c16 * 16) ^ ((row & 7) << 4)),
            (const char*)&g_encT[b][row][c16 * 8]);
    }
    CPC();

    #pragma unroll 1
    for (int it = 0; it < 64; it++) {
        const int n = it >> 3, kk = it & 7;
        const uint32_t bufo = (uint32_t)(it & 1) * 32768u;

        if (kk == 0) {
            #pragma unroll
            for (int mt = 0; mt < 2; mt++)
                #pragma unroll
                for (int nt = 0; nt < 8; nt++)
                    acc[mt][nt][0] = acc[mt][nt][1] = acc[mt][nt][2] = acc[mt][nt][3] = 0.f;
        }

        if (it < 63) {
            const int n2 = (it + 1) >> 3, k2 = (it + 1) & 7;
            const uint32_t bo2 = (uint32_t)((it + 1) & 1) * 32768u;
            #pragma unroll
            for (int j = 0; j < 4; j++) {
                int lin = j * 512 + tid;
                int row = lin >> 3, c16 = lin & 7;
                CPA(sBu + bo2 + row * 128 + ((c16 * 16) ^ ((row & 7) << 4)),
                    (const char*)&g_encT[b][n2 * 256 + row][k2 * 64 + c16 * 8]);
            }
            CPC();
            CPW(1);
        } else {
            CPW(0);
        }
        __syncthreads();

        const uint32_t aB = sAu + kk * 16384;
        #pragma unroll
        for (int ks = 0; ks < 4; ks++) {
            const int k0b = ks * 32;
            uint32_t a[2][4], bfr[4][4];
            #pragma unroll
            for (int mt = 0; mt < 2; mt++)
                ldsm4(a[mt], aB + (wm + mt * 16 + arow) * 128 + ((k0b + acolb) ^ swz));
            #pragma unroll
            for (int ng = 0; ng < 4; ng++)
                ldsm4(bfr[ng], sBu + bufo + (wn + ng * 16 + brow) * 128 + ((k0b + bcolb) ^ swz));
            #pragma unroll
            for (int mt = 0; mt < 2; mt++)
                #pragma unroll
                for (int ng = 0; ng < 4; ng++) {
                    mma16816(acc[mt][2 * ng],     a[mt], &bfr[ng][0]);
                    mma16816(acc[mt][2 * ng + 1], a[mt], &bfr[ng][2]);
                }
        }
        __syncthreads();   // protect buffer before re-stage next iteration

        if (kk == 7) {     // epilogue: exp, store P, accumulate Z
            const int sg = n * 256 + wn;
            #pragma unroll
            for (int mt = 0; mt < 2; mt++) {
                const int r0 = l0 + wm + mt * 16 + (lane >> 2);
                #pragma unroll
                for (int nt = 0; nt < 8; nt++) {
                    const int sc = sg + nt * 8 + ((lane & 3) << 1);
                    float e0 = __expf(acc[mt][nt][0]);
                    float e1 = __expf(acc[mt][nt][1]);
                    float e2 = __expf(acc[mt][nt][2]);
                    float e3 = __expf(acc[mt][nt][3]);
                    zr[mt][0] += e0 + e1;
                    zr[mt][1] += e2 + e3;
                    *(__half2*)&g_P[b][r0][sc]     = __floats2half2_rn(e0, e1);
                    *(__half2*)&g_P[b][r0 + 8][sc] = __floats2half2_rn(e2, e3);
                }
            }
        }
    }

    #pragma unroll
    for (int mt = 0; mt < 2; mt++) {
        atomicAdd(&zs[wm + mt * 16 + (lane >> 2)],     zr[mt][0]);
        atomicAdd(&zs[wm + mt * 16 + (lane >> 2) + 8], zr[mt][1]);
    }
    __syncthreads();
    if (tid < 128) g_Zinv[b][l0 + tid] = 1.0f / zs[tid];
}

// ---------------- K2: context + classifier ----------------
// CTA: 128 labels x 256 channels, K=S=2048 in chunks of 64. 512 threads, 16 warps.
#define K2_SMEM (512 + 2 * 16384 + 2 * 32768)

__global__ __launch_bounds__(512, 1) void k2_context(const float* __restrict__ W_cls,
                                                     float* __restrict__ out) {
    extern __shared__ char sm[];
    float* red = (float*)sm;
    char* sA = sm + 512;
    char* sB = sm + 512 + 32768;
    const uint32_t sAu = smem_u32(sA), sBu = smem_u32(sB);
    const int tid = threadIdx.x, lane = tid & 31, wid = tid >> 5;
    const int wm = (wid >> 2) * 32, wn = (wid & 3) * 64;
    const int b = blockIdx.z, l0 = blockIdx.x * 128, c0 = blockIdx.y * 256;

    if (tid < 128) red[tid] = 0.f;

    const int swz   = (lane & 7) << 4;
    const int arow  = lane & 15;
    const int acolb = (lane >> 4) << 4;
    const int brow  = (lane & 7) + ((lane >> 4) << 3);
    const int bcolb = ((lane >> 3) & 1) << 4;

    float acc[2][8][4];
    #pragma unroll
    for (int mt = 0; mt < 2; mt++)
        #pragma unroll
        for (int nt = 0; nt < 8; nt++)
            acc[mt][nt][0] = acc[mt][nt][1] = acc[mt][nt][2] = acc[mt][nt][3] = 0.f;

    // prologue stage it=0
    #pragma unroll
    for (int j = 0; j < 2; j++) {
        int lin = j * 512 + tid;
        int row = lin >> 3, c16 = lin & 7;
        CPA(sAu + row * 128 + ((c16 * 16) ^ ((row & 7) << 4)),
            (const char*)&g_P[b][l0 + row][c16 * 8]);
    }
    #pragma unroll
    for (int j = 0; j < 4; j++) {
        int lin = j * 512 + tid;
        int row = lin >> 3, c16 = lin & 7;
        CPA(sBu + row * 128 + ((c16 * 16) ^ ((row & 7) << 4)),
            (const char*)&g_encB[b][c0 + row][c16 * 8]);
    }
    CPC();

    #pragma unroll 1
    for (int it = 0; it < 32; it++) {
        const uint32_t aBuf = (uint32_t)(it & 1) * 16384u;
        const uint32_t bBuf = (uint32_t)(it & 1) * 32768u;

        if (it < 31) {
            const int s2 = (it + 1) * 64;
            const uint32_t a2 = (uint32_t)((it + 1) & 1) * 16384u;
            const uint32_t b2 = (uint32_t)((it + 1) & 1) * 32768u;
            #pragma unroll
            for (int j = 0; j < 2; j++) {
                int lin = j * 512 + tid;
                int row = lin >> 3, c16 = lin & 7;
                CPA(sAu + a2 + row * 128 + ((c16 * 16) ^ ((row & 7) << 4)),
                    (const char*)&g_P[b][l0 + row][s2 + c16 * 8]);
            }
            #pragma unroll
            for (int j = 0; j < 4; j++) {
                int lin = j * 512 + tid;
                int row = lin >> 3, c16 = lin & 7;
                CPA(sBu + b2 + row * 128 + ((c16 * 16) ^ ((row & 7) << 4)),
                    (const char*)&g_encB[b][c0 + row][s2 + c16 * 8]);
            }
            CPC();
            CPW(1);
        } else {
            CPW(0);
        }
        __syncthreads();

        #pragma unroll
        for (int ks = 0; ks < 4; ks++) {
            const int k0b = ks * 32;
            uint32_t a[2][4], bfr[4][4];
            #pragma unroll
            for (int mt = 0; mt < 2; mt++)
                ldsm4(a[mt], sAu + aBuf + (wm + mt * 16 + arow) * 128 + ((k0b + acolb) ^ swz));
            #pragma unroll
            for (int ng = 0; ng < 4; ng++)
                ldsm4(bfr[ng], sBu + bBuf + (wn + ng * 16 + brow) * 128 + ((k0b + bcolb) ^ swz));
            #pragma unroll
            for (int mt = 0; mt < 2; mt++)
                #pragma unroll
                for (int ng = 0; ng < 4; ng++) {
                    mma16816(acc[mt][2 * ng],     a[mt], &bfr[ng][0]);
                    mma16816(acc[mt][2 * ng + 1], a[mt], &bfr[ng][2]);
                }
        }
        __syncthreads();
    }

    // epilogue: diagonal classifier dot + CTA reduce + global atomic
    #pragma unroll
    for (int mt = 0; mt < 2; mt++) {
        const int lloc = wm + mt * 16 + (lane >> 2);
        const int gl0 = l0 + lloc, gl1 = gl0 + 8;
        float v0 = 0.f, v1 = 0.f;
        #pragma unroll
        for (int nt = 0; nt < 8; nt++) {
            const int c = c0 + wn + nt * 8 + ((lane & 3) << 1);
            if (gl0 < L_) {
                const float* w = &W_cls[(size_t)gl0 * C_ + c];
                v0 += acc[mt][nt][0] * w[0] + acc[mt][nt][1] * w[1];
            }
            if (gl1 < L_) {
                const float* w = &W_cls[(size_t)gl1 * C_ + c];
                v1 += acc[mt][nt][2] * w[0] + acc[mt][nt][3] * w[1];
            }
        }
        atomicAdd(&red[lloc],     v0);
        atomicAdd(&red[lloc + 8], v1);
    }
    __syncthreads();
    if (tid < 128) {
        const int gl = l0 + tid;
        if (gl < L_)
            atomicAdd(&out[(size_t)b * L_ + gl], red[tid] * g_Zinv[b][gl]);
    }
}

// ---------------- launcher ----------------
extern "C" void kernel_launch(void* const* d_in, const int* in_sizes, int n_in,
                              void* d_out, int out_size) {
    const float* encoded = (const float*)d_in[0];
    const float* W_attn  = (const float*)d_in[1];
    // d_in[2] = b_attn: constant along the softmax axis -> no effect on output
    const float* W_cls   = (const float*)d_in[3];
    const float* b_cls   = (const float*)d_in[4];
    float* out = (float*)d_out;

    cudaFuncSetAttribute(k1_scores,  cudaFuncAttributeMaxDynamicSharedMemorySize, K1_SMEM);
    cudaFuncSetAttribute(k2_context, cudaFuncAttributeMaxDynamicSharedMemorySize, K2_SMEM);

    prep_enc<<<dim3(C_ / 32, S_ / 32, B_), 256>>>(encoded);
    prep_w<<<(LPAD * C_) / 256, 256>>>(W_attn);
    out_init<<<(B_ * L_ + 255) / 256, 256>>>(b_cls, out);
    k1_scores<<<dim3(NLT, B_), 512, K1_SMEM>>>();
    k2_context<<<dim3(NLT, 2, B_), 512, K2_SMEM>>>(W_cls, out);
}